// round 13
// baseline (speedup 1.0000x reference)
#include <cuda_runtime.h>
#include <cuda_bf16.h>
#include <math_constants.h>
#include <cstdint>
#include <cstddef>

// Problem constants
constexpr int B_  = 128;
constexpr int T_  = 256;
constexpr int C_  = 384;
constexpr int H_  = 6;
constexpr int D_  = 64;
constexpr int FF_ = 1536;
constexpr int M_  = B_ * T_;     // 32768
constexpr int KL1 = 3 * C_;      // 1152 logical K (3-term)
constexpr int KL2 = 3 * FF_;     // 4608
constexpr int KW1 = 2 * C_;      // 768  physical [hi|lo] width
constexpr int KW4 = 2 * FF_;     // 3072
constexpr int BH_ = B_ * H_;     // 768

// ---------------- scratch ----------------
__device__ __nv_bfloat16 g_acatA[(size_t)M_ * KW1];      // [hi|lo]
__device__ __nv_bfloat16 g_acat4[(size_t)M_ * KW4];      // [hi|lo]
__device__ __nv_bfloat16 g_bqkv [(size_t)(3 * C_) * KL1]; // weights keep [hi|hi|lo]
__device__ __nv_bfloat16 g_bcp  [(size_t)C_  * KL1];
__device__ __nv_bfloat16 g_bc1  [(size_t)FF_ * KL1];
__device__ __nv_bfloat16 g_bc2  [(size_t)C_  * KL2];
__device__ float g_biasqkv[3 * C_];
__device__ __nv_bfloat16 g_kc[(size_t)BH_ * T_ * 128];   // K [hi|lo] along d
__device__ __nv_bfloat16 g_qc[(size_t)BH_ * T_ * 128];   // Q [hi|lo] along d
__device__ __nv_bfloat16 g_vt[(size_t)BH_ * 64 * 512];   // V^T [hi|lo] along s
__device__ float g_x1 [M_ * C_];

// ---------------- helpers ----------------
__device__ __forceinline__ uint32_t smem_u32(const void* p) {
    uint32_t a;
    asm("{ .reg .u64 t; cvta.to.shared.u64 t, %1; cvt.u32.u64 %0, t; }" : "=r"(a) : "l"(p));
    return a;
}
__device__ __forceinline__ void cp16(uint32_t dst, const void* src) {
    asm volatile("cp.async.cg.shared.global [%0], [%1], 16;" :: "r"(dst), "l"(src));
}
#define CP_COMMIT() asm volatile("cp.async.commit_group;" ::: "memory")
#define CP_WAIT0()  asm volatile("cp.async.wait_group 0;"  ::: "memory")
#define CP_WAIT1()  asm volatile("cp.async.wait_group 1;"  ::: "memory")
#define CP_WAIT2()  asm volatile("cp.async.wait_group 2;"  ::: "memory")

__device__ __forceinline__ void ldm_x4(uint32_t* r, uint32_t addr) {
    asm volatile("ldmatrix.sync.aligned.m8n8.x4.shared.b16 {%0,%1,%2,%3}, [%4];"
        : "=r"(r[0]), "=r"(r[1]), "=r"(r[2]), "=r"(r[3]) : "r"(addr));
}
__device__ __forceinline__ void mma16816(float* c, const uint32_t* a, uint32_t b0, uint32_t b1) {
    asm volatile("mma.sync.aligned.m16n8k16.row.col.f32.bf16.bf16.f32 "
        "{%0,%1,%2,%3}, {%4,%5,%6,%7}, {%8,%9}, {%0,%1,%2,%3};"
        : "+f"(c[0]), "+f"(c[1]), "+f"(c[2]), "+f"(c[3])
        : "r"(a[0]), "r"(a[1]), "r"(a[2]), "r"(a[3]), "r"(b0), "r"(b1));
}
__device__ __forceinline__ void split2(float v, __nv_bfloat16& hi, __nv_bfloat16& lo) {
    hi = __float2bfloat16(v);
    lo = __float2bfloat16(v - __bfloat162float(hi));
}
__device__ __forceinline__ uint32_t pack2(__nv_bfloat16 a, __nv_bfloat16 b) {
    __nv_bfloat162 p(a, b);
    return *(uint32_t*)&p;
}

// ---------------- LayerNorm -> split activation [hi|lo] ----------------
__global__ void ln_split_kernel(const float* __restrict__ x, const float* __restrict__ g,
                                const float* __restrict__ b, __nv_bfloat16* __restrict__ acat)
{
    int row = blockIdx.x;
    const float* xr = x + (size_t)row * C_;
    int tid = threadIdx.x;
    float v0 = xr[tid], v1 = xr[tid + 128], v2 = xr[tid + 256];
    float s  = v0 + v1 + v2;
    float sq = v0 * v0 + v1 * v1 + v2 * v2;
    #pragma unroll
    for (int o = 16; o; o >>= 1) {
        s  += __shfl_xor_sync(0xffffffffu, s,  o);
        sq += __shfl_xor_sync(0xffffffffu, sq, o);
    }
    __shared__ float red[2][4];
    int wid = tid >> 5, lane = tid & 31;
    if (lane == 0) { red[0][wid] = s; red[1][wid] = sq; }
    __syncthreads();
    s  = red[0][0] + red[0][1] + red[0][2] + red[0][3];
    sq = red[1][0] + red[1][1] + red[1][2] + red[1][3];
    float mu  = s * (1.0f / C_);
    float var = sq * (1.0f / C_) - mu * mu;
    float inv = rsqrtf(var + 1e-5f);
    __nv_bfloat16* orow = acat + (size_t)row * KW1;
    #pragma unroll
    for (int u = 0; u < 3; u++) {
        int k = tid + u * 128;
        float vv = (u == 0 ? v0 : (u == 1 ? v1 : v2));
        float y = (vv - mu) * inv * g[k] + b[k];
        __nv_bfloat16 hi, lo; split2(y, hi, lo);
        orow[k] = hi; orow[C_ + k] = lo;
    }
}

// ---------------- weight builders (B keeps [hi|hi|lo], 3K wide) ---------------
__global__ void build_bcat_kernel(const float* __restrict__ W, __nv_bfloat16* __restrict__ Bcat,
                                  int K, int N)
{
    size_t idx = (size_t)blockIdx.x * 256 + threadIdx.x;
    if (idx >= (size_t)K * N) return;
    int n = (int)(idx / K);
    int k = (int)(idx % K);
    float v = W[(size_t)k * N + n];
    __nv_bfloat16 hi, lo; split2(v, hi, lo);
    size_t base = (size_t)n * 3 * K;
    Bcat[base + k] = hi; Bcat[base + K + k] = hi; Bcat[base + 2 * K + k] = lo;
}

__global__ void build_bcat_qkv_kernel(const float* __restrict__ Wk, const float* __restrict__ Wq,
                                      const float* __restrict__ Wv, __nv_bfloat16* __restrict__ Bcat)
{
    size_t idx = (size_t)blockIdx.x * 256 + threadIdx.x;
    if (idx >= (size_t)(3 * C_) * C_) return;
    int n = (int)(idx / C_);
    int k = (int)(idx % C_);
    int sel = n / C_;
    int nn = n - sel * C_;
    int h = nn >> 6, d = nn & 63;
    const float* Ws = (sel == 0) ? Wk : (sel == 1) ? Wq : Wv;
    float v = Ws[((size_t)h * C_ + k) * 64 + d];
    __nv_bfloat16 hi, lo; split2(v, hi, lo);
    size_t base = (size_t)n * KL1;
    Bcat[base + k] = hi; Bcat[base + C_ + k] = hi; Bcat[base + 2 * C_ + k] = lo;
}

__global__ void bias_concat_kernel(const float* __restrict__ bk, const float* __restrict__ bq,
                                   const float* __restrict__ bv, float* __restrict__ out)
{
    int t = blockIdx.x * 256 + threadIdx.x;
    if (t >= 3 * C_) return;
    int sel = t / C_, nn = t % C_;
    out[t] = (sel == 0 ? bk : sel == 1 ? bq : bv)[nn];
}

// ---------------- mma.sync GEMM: 128x128, BK=32, 4-stage async pipeline -------
// (R9-winning configuration: 80KB smem, 2 CTAs/SM)
constexpr uint32_t G_ASTG = 128u * 80;        // 10240 bytes per stage (one operand)
constexpr uint32_t G_BOFF = 4u * G_ASTG;      // B region offset
constexpr int GEMM_SMEM = (int)(8u * G_ASTG); // 81920

template<int FLAGS>
__global__ void __launch_bounds__(256)
mma_gemm(const __nv_bfloat16* __restrict__ A, const __nv_bfloat16* __restrict__ Bc,
         const float* __restrict__ bias, const float* __restrict__ resid,
         float* __restrict__ out0, float* __restrict__ out1, float* __restrict__ out2,
         __nv_bfloat16* __restrict__ acat_out, int Klog, int Aw, int N)
{
    extern __shared__ char gsm[];
    uint32_t sb = smem_u32(gsm);

    int tid  = threadIdx.x;
    int wid  = tid >> 5;
    int lane = tid & 31;
    int wm = wid >> 2;
    int wn = wid & 3;
    int m0 = blockIdx.y * 128;
    int n0 = blockIdx.x * 128;
    int NC  = Klog / 32;
    int KQ2 = (Klog / 96) * 2;     // chunks covering phys [hi|lo]

    int lrow = tid >> 2;
    int lseg = tid & 3;
    const __nv_bfloat16* aBase0 = A  + (size_t)(m0 + lrow)      * Aw + lseg * 8;
    const __nv_bfloat16* aBase1 = A  + (size_t)(m0 + lrow + 64) * Aw + lseg * 8;
    const __nv_bfloat16* bBase0 = Bc + (size_t)(n0 + lrow)      * Klog + lseg * 8;
    const __nv_bfloat16* bBase1 = Bc + (size_t)(n0 + lrow + 64) * Klog + lseg * 8;

    uint32_t dA0 = sb + lrow * 80 + lseg * 16;
    uint32_t dA1 = dA0 + 64 * 80;
    uint32_t dB0 = dA0 + G_BOFF;
    uint32_t dB1 = dA1 + G_BOFF;

    auto load_chunk = [&](int c, int st) {
        int pc = (c < KQ2) ? c : c - KQ2;
        uint32_t o = (uint32_t)st * G_ASTG;
        cp16(dA0 + o, aBase0 + (size_t)pc * 32);
        cp16(dA1 + o, aBase1 + (size_t)pc * 32);
        cp16(dB0 + o, bBase0 + (size_t)c * 32);
        cp16(dB1 + o, bBase1 + (size_t)c * 32);
    };

    int q = lane >> 3, i = lane & 7;
    uint32_t aOff = sb + (wm * 64 + (q & 1) * 8 + i) * 80 + (q >> 1) * 16;
    uint32_t bOff = sb + G_BOFF + (wn * 32 + (q >> 1) * 8 + i) * 80 + (q & 1) * 16;

    float acc[4][4][4];
    #pragma unroll
    for (int mt = 0; mt < 4; mt++)
        #pragma unroll
        for (int nt = 0; nt < 4; nt++)
            #pragma unroll
            for (int r = 0; r < 4; r++) acc[mt][nt][r] = 0.0f;

    #pragma unroll
    for (int s = 0; s < 3; s++) { load_chunk(s, s); CP_COMMIT(); }

    for (int c = 0; c < NC; c++) {
        int st = c & 3;
        CP_WAIT2();
        __syncthreads();
        if (c + 3 < NC) load_chunk(c + 3, (c + 3) & 3);
        CP_COMMIT();

        uint32_t aS = aOff + (uint32_t)st * G_ASTG;
        uint32_t bS = bOff + (uint32_t)st * G_ASTG;
        #pragma unroll
        for (int ks = 0; ks < 2; ks++) {
            uint32_t af[4][4], bf[2][4];
            #pragma unroll
            for (int mt = 0; mt < 4; mt++)
                ldm_x4(af[mt], aS + mt * 16 * 80 + ks * 32);
            #pragma unroll
            for (int p = 0; p < 2; p++)
                ldm_x4(bf[p], bS + p * 16 * 80 + ks * 32);
            #pragma unroll
            for (int mt = 0; mt < 4; mt++)
                #pragma unroll
                for (int nt = 0; nt < 4; nt++)
                    mma16816(acc[mt][nt], af[mt], bf[nt >> 1][(nt & 1) * 2],
                             bf[nt >> 1][(nt & 1) * 2 + 1]);
        }
    }

    // ---------------- epilogue ----------------
    int mrow = lane >> 2;
    int ncl  = (lane & 3) * 2;
    #pragma unroll
    for (int mt = 0; mt < 4; mt++) {
        #pragma unroll
        for (int half = 0; half < 2; half++) {
            int m = m0 + wm * 64 + mt * 16 + mrow + half * 8;
            #pragma unroll
            for (int nt = 0; nt < 4; nt++) {
                int n = n0 + wn * 32 + nt * 8 + ncl;
                float v0 = acc[mt][nt][half * 2 + 0] + bias[n];
                float v1 = acc[mt][nt][half * 2 + 1] + bias[n + 1];
                if (FLAGS == 1) {
                    int sel = n / C_;
                    int nn = n - sel * C_;
                    int b_ = m >> 8, t = m & 255;
                    int hh = nn >> 6, d0 = nn & 63;
                    int bh = b_ * H_ + hh;
                    __nv_bfloat16 h0, l0, h1, l1;
                    split2(v0, h0, l0); split2(v1, h1, l1);
                    if (sel == 0) {                     // K [hi|lo], width 128
                        __nv_bfloat16* p = (__nv_bfloat16*)out0 +
                            ((size_t)bh * T_ + t) * 128 + d0;
                        *(uint32_t*)(p)      = pack2(h0, h1);
                        *(uint32_t*)(p + 64) = pack2(l0, l1);
                    } else if (sel == 1) {              // Q [hi|lo], width 128
                        __nv_bfloat16* p = (__nv_bfloat16*)out1 +
                            ((size_t)bh * T_ + t) * 128 + d0;
                        *(uint32_t*)(p)      = pack2(h0, h1);
                        *(uint32_t*)(p + 64) = pack2(l0, l1);
                    } else {                            // V^T [hi|lo] along s, width 512
                        __nv_bfloat16* p0 = (__nv_bfloat16*)out2 +
                            ((size_t)bh * 64 + d0) * 512 + t;
                        p0[0] = h0; p0[256] = l0;
                        __nv_bfloat16* p1 = p0 + 512;
                        p1[0] = h1; p1[256] = l1;
                    }
                } else if (FLAGS == 2) {
                    v0 = fmaxf(v0, 0.0f); v1 = fmaxf(v1, 0.0f);
                    __nv_bfloat16 h0, l0, h1, l1;
                    split2(v0, h0, l0); split2(v1, h1, l1);
                    __nv_bfloat16* rowp = acat_out + (size_t)m * KW4 + n;
                    *(uint32_t*)(rowp)       = pack2(h0, h1);
                    *(uint32_t*)(rowp + FF_) = pack2(l0, l1);
                } else {
                    if (FLAGS & 4) {
                        const float2 rv = *(const float2*)(resid + (size_t)m * N + n);
                        v0 += rv.x; v1 += rv.y;
                    }
                    *(float2*)(out0 + (size_t)m * N + n) = make_float2(v0, v1);
                }
            }
        }
    }
}

// ---------------- flash attention: phys [hi|lo] smem, double-buffered Q/V ------
// stride 272B (odd multiple of 16B -> conflict-free). ~136KB smem, 1 CTA/SM.
constexpr uint32_t AOFF_K = 0;                          // 128 rows
constexpr uint32_t AQSTG  = 64u * 272;                  // 17408 per stage
constexpr uint32_t AOFF_Q = 128u * 272;                 // 34816 (2 stages)
constexpr uint32_t AOFF_V = AOFF_Q + 2 * AQSTG;         // 69632 (2 stages)
constexpr uint32_t AOFF_P = AOFF_V + 2 * AQSTG;         // 104448 (128 rows)
constexpr int ATTN2_SMEM = (int)(AOFF_P + 128u * 272);  // 139264

__global__ void __launch_bounds__(256)
attn_mma(const __nv_bfloat16* __restrict__ Kc, const __nv_bfloat16* __restrict__ Qc,
         const __nv_bfloat16* __restrict__ Vt, __nv_bfloat16* __restrict__ acat)
{
    extern __shared__ char smb[];
    uint32_t sb = smem_u32(smb);
    int tid = threadIdx.x, wid = tid >> 5, lane = tid & 31;
    int tt = blockIdx.x, h = blockIdx.y, b = blockIdx.z;
    int bh = b * H_ + h;
    const __nv_bfloat16* Kg = Kc + ((size_t)bh * T_ + (size_t)tt * 128) * 128;
    const __nv_bfloat16* Qg = Qc + (size_t)bh * T_ * 128;
    const __nv_bfloat16* Vg = Vt + (size_t)bh * 64 * 512;

    // K tile: 128 rows x 16 chunks (phys 128 cols)
    #pragma unroll
    for (int it = 0; it < 8; it++) {
        int ch = tid + it * 256;
        int r = ch >> 4, c = ch & 15;
        cp16(sb + AOFF_K + r * 272 + c * 16, Kg + (size_t)r * 128 + c * 8);
    }
    CP_COMMIT();

    int nst = tt * 2 + 2;
    auto loadQV = [&](int st) {
        int stg = st & 1;
        const __nv_bfloat16* Qt = Qg + (size_t)st * 64 * 128;
        #pragma unroll
        for (int it = 0; it < 4; it++) {
            int ch = tid + it * 256;
            int r = ch >> 4, c = ch & 15;
            cp16(sb + AOFF_Q + stg * AQSTG + r * 272 + c * 16, Qt + (size_t)r * 128 + c * 8);
        }
        #pragma unroll
        for (int it = 0; it < 4; it++) {
            int ch = tid + it * 256;
            int r = ch >> 4, c = ch & 15;
            int seg = c >> 3, j = c & 7;
            int gcol = seg * 256 + st * 64 + j * 8;
            cp16(sb + AOFF_V + stg * AQSTG + r * 272 + c * 16, Vg + (size_t)r * 512 + gcol);
        }
        CP_COMMIT();
    };
    loadQV(0);

    float m_run[2] = { -CUDART_INF_F, -CUDART_INF_F };
    float l_run[2] = { 0.0f, 0.0f };
    float oacc[8][4];
    #pragma unroll
    for (int nt = 0; nt < 8; nt++)
        #pragma unroll
        for (int e = 0; e < 4; e++) oacc[nt][e] = 0.0f;

    const float scl = rsqrtf((float)C_);
    int q = lane >> 3, i5 = lane & 7;
    uint32_t aK = sb + AOFF_K + (wid * 16 + (q & 1) * 8 + i5) * 272 + (q >> 1) * 16;
    uint32_t aP = sb + AOFF_P + (wid * 16 + (q & 1) * 8 + i5) * 272 + (q >> 1) * 16;
    uint32_t bQ = sb + AOFF_Q + ((q >> 1) * 8 + i5) * 272 + (q & 1) * 16;
    uint32_t bV = sb + AOFF_V + ((q >> 1) * 8 + i5) * 272 + (q & 1) * 16;

    int r0 = lane >> 2;
    int tg0 = tt * 128 + wid * 16 + r0;
    int tg1 = tg0 + 8;
    __nv_bfloat16* sP = (__nv_bfloat16*)(smb + AOFF_P);

    for (int st = 0; st < nst; st++) {
        int stg = st & 1;
        if (st + 1 < nst) { loadQV(st + 1); CP_WAIT1(); } else { CP_WAIT0(); }
        __syncthreads();

        // S = K . Q : logical k'=192 (12 steps); A remap [hi|lo|hi], B remap [hi|hi|lo]
        float sacc[8][4];
        #pragma unroll
        for (int nt = 0; nt < 8; nt++)
            #pragma unroll
            for (int e = 0; e < 4; e++) sacc[nt][e] = 0.0f;
        #pragma unroll
        for (int ks = 0; ks < 12; ks++) {
            int ka = (ks < 8) ? ks : ks - 8;      // [hi|lo|hi]
            int kb = (ks < 4) ? ks : ks - 4;      // [hi|hi|lo]
            uint32_t af[4], bf[4][4];
            ldm_x4(af, aK + ka * 32);
            #pragma unroll
            for (int p = 0; p < 4; p++)
                ldm_x4(bf[p], bQ + stg * AQSTG + p * 16 * 272 + kb * 32);
            #pragma unroll
            for (int nt = 0; nt < 8; nt++)
                mma16816(sacc[nt], af, bf[nt >> 1][(nt & 1) * 2],
                         bf[nt >> 1][(nt & 1) * 2 + 1]);
        }

        float mx0 = -CUDART_INF_F, mx1 = -CUDART_INF_F;
        #pragma unroll
        for (int nt = 0; nt < 8; nt++) {
            #pragma unroll
            for (int e = 0; e < 2; e++) {
                int sg = st * 64 + nt * 8 + (lane & 3) * 2 + e;
                float v0 = sacc[nt][e] * scl;
                if (sg > tg0) v0 = -CUDART_INF_F;
                sacc[nt][e] = v0; mx0 = fmaxf(mx0, v0);
                float v1 = sacc[nt][2 + e] * scl;
                if (sg > tg1) v1 = -CUDART_INF_F;
                sacc[nt][2 + e] = v1; mx1 = fmaxf(mx1, v1);
            }
        }
        mx0 = fmaxf(mx0, __shfl_xor_sync(0xffffffffu, mx0, 1));
        mx0 = fmaxf(mx0, __shfl_xor_sync(0xffffffffu, mx0, 2));
        mx1 = fmaxf(mx1, __shfl_xor_sync(0xffffffffu, mx1, 1));
        mx1 = fmaxf(mx1, __shfl_xor_sync(0xffffffffu, mx1, 2));

        float mn0 = fmaxf(m_run[0], mx0), mn1 = fmaxf(m_run[1], mx1);
        float es0 = __expf(m_run[0] - mn0), es1 = __expf(m_run[1] - mn1);
        m_run[0] = mn0; m_run[1] = mn1;

        float sum0 = 0.0f, sum1 = 0.0f;
        #pragma unroll
        for (int nt = 0; nt < 8; nt++) {
            #pragma unroll
            for (int e = 0; e < 2; e++) {
                float p0 = __expf(sacc[nt][e] - mn0);     sacc[nt][e] = p0;     sum0 += p0;
                float p1 = __expf(sacc[nt][2 + e] - mn1); sacc[nt][2 + e] = p1; sum1 += p1;
            }
        }
        sum0 += __shfl_xor_sync(0xffffffffu, sum0, 1);
        sum0 += __shfl_xor_sync(0xffffffffu, sum0, 2);
        sum1 += __shfl_xor_sync(0xffffffffu, sum1, 1);
        sum1 += __shfl_xor_sync(0xffffffffu, sum1, 2);
        l_run[0] = l_run[0] * es0 + sum0;
        l_run[1] = l_run[1] * es1 + sum1;

        #pragma unroll
        for (int nt = 0; nt < 8; nt++) {
            oacc[nt][0] *= es0; oacc[nt][1] *= es0;
            oacc[nt][2] *= es1; oacc[nt][3] *= es1;
        }

        // write P phys [hi|lo] (136 bf16 row stride)
        #pragma unroll
        for (int nt = 0; nt < 8; nt++) {
            int cb = nt * 8 + (lane & 3) * 2;
            __nv_bfloat16 h0, l0, h1, l1;
            split2(sacc[nt][0], h0, l0); split2(sacc[nt][1], h1, l1);
            __nv_bfloat16* pr = sP + (wid * 16 + r0) * 136 + cb;
            *(uint32_t*)(pr)      = pack2(h0, h1);
            *(uint32_t*)(pr + 64) = pack2(l0, l1);
            split2(sacc[nt][2], h0, l0); split2(sacc[nt][3], h1, l1);
            __nv_bfloat16* pr2 = pr + 8 * 136;
            *(uint32_t*)(pr2)      = pack2(h0, h1);
            *(uint32_t*)(pr2 + 64) = pack2(l0, l1);
        }
        __syncthreads();

        // O += P . V : A remap [hi|lo|hi], B remap [hi|hi|lo]
        #pragma unroll
        for (int ks = 0; ks < 12; ks++) {
            int ka = (ks < 8) ? ks : ks - 8;
            int kb = (ks < 4) ? ks : ks - 4;
            uint32_t af[4], bf[4][4];
            ldm_x4(af, aP + ka * 32);
            #pragma unroll
            for (int p = 0; p < 4; p++)
                ldm_x4(bf[p], bV + stg * AQSTG + p * 16 * 272 + kb * 32);
            #pragma unroll
            for (int nt = 0; nt < 8; nt++)
                mma16816(oacc[nt], af, bf[nt >> 1][(nt & 1) * 2],
                         bf[nt >> 1][(nt & 1) * 2 + 1]);
        }
        __syncthreads();
    }

    // epilogue: normalize, split, write acatA [hi|lo] rows directly
    float inv0 = 1.0f / l_run[0], inv1 = 1.0f / l_run[1];
    int t0 = tt * 128 + wid * 16 + r0;
    size_t mrow0 = (size_t)(b * T_ + t0) * KW1;
    size_t mrow1 = mrow0 + (size_t)8 * KW1;
    #pragma unroll
    for (int nt = 0; nt < 8; nt++) {
        int k = h * 64 + nt * 8 + (lane & 3) * 2;
        {
            float v0 = oacc[nt][0] * inv0, v1 = oacc[nt][1] * inv0;
            __nv_bfloat16 h0, l0, h1, l1;
            split2(v0, h0, l0); split2(v1, h1, l1);
            __nv_bfloat16* p = g_acatA + mrow0 + k;
            *(uint32_t*)(p)      = pack2(h0, h1);
            *(uint32_t*)(p + C_) = pack2(l0, l1);
        }
        {
            float v0 = oacc[nt][2] * inv1, v1 = oacc[nt][3] * inv1;
            __nv_bfloat16 h0, l0, h1, l1;
            split2(v0, h0, l0); split2(v1, h1, l1);
            __nv_bfloat16* p = g_acatA + mrow1 + k;
            *(uint32_t*)(p)      = pack2(h0, h1);
            *(uint32_t*)(p + C_) = pack2(l0, l1);
        }
    }
}

// ---------------- host orchestration -------------------------------------------
extern "C" void kernel_launch(void* const* d_in, const int* in_sizes, int n_in,
                              void* d_out, int out_size)
{
    const float* x     = (const float*)d_in[0];
    const float* ln1_g = (const float*)d_in[1];
    const float* ln1_b = (const float*)d_in[2];
    const float* Wk    = (const float*)d_in[3];
    const float* bk    = (const float*)d_in[4];
    const float* Wq    = (const float*)d_in[5];
    const float* bq    = (const float*)d_in[6];
    const float* Wv    = (const float*)d_in[7];
    const float* bv    = (const float*)d_in[8];
    const float* Wp    = (const float*)d_in[9];
    const float* bp    = (const float*)d_in[10];
    const float* ln2_g = (const float*)d_in[11];
    const float* ln2_b = (const float*)d_in[12];
    const float* W1    = (const float*)d_in[13];
    const float* b1    = (const float*)d_in[14];
    const float* W2    = (const float*)d_in[15];
    const float* b2    = (const float*)d_in[16];
    float* out = (float*)d_out;

    __nv_bfloat16 *acatA, *acat4, *bqkv, *bcp, *bc1, *bc2, *kc, *qc, *vt;
    float *biasqkv, *x1;
    cudaGetSymbolAddress((void**)&acatA,   g_acatA);
    cudaGetSymbolAddress((void**)&acat4,   g_acat4);
    cudaGetSymbolAddress((void**)&bqkv,    g_bqkv);
    cudaGetSymbolAddress((void**)&bcp,     g_bcp);
    cudaGetSymbolAddress((void**)&bc1,     g_bc1);
    cudaGetSymbolAddress((void**)&bc2,     g_bc2);
    cudaGetSymbolAddress((void**)&biasqkv, g_biasqkv);
    cudaGetSymbolAddress((void**)&kc,  g_kc);
    cudaGetSymbolAddress((void**)&qc,  g_qc);
    cudaGetSymbolAddress((void**)&vt,  g_vt);
    cudaGetSymbolAddress((void**)&x1,  g_x1);

    cudaFuncSetAttribute(attn_mma, cudaFuncAttributeMaxDynamicSharedMemorySize, ATTN2_SMEM);
    cudaFuncSetAttribute(mma_gemm<1>, cudaFuncAttributeMaxDynamicSharedMemorySize, GEMM_SMEM);
    cudaFuncSetAttribute(mma_gemm<2>, cudaFuncAttributeMaxDynamicSharedMemorySize, GEMM_SMEM);
    cudaFuncSetAttribute(mma_gemm<4>, cudaFuncAttributeMaxDynamicSharedMemorySize, GEMM_SMEM);

    // weight / bias conversions
    bias_concat_kernel<<<5, 256>>>(bk, bq, bv, biasqkv);
    build_bcat_qkv_kernel<<<(3 * C_ * C_ + 255) / 256, 256>>>(Wk, Wq, Wv, bqkv);
    build_bcat_kernel<<<(C_ * C_ + 255) / 256, 256>>>(Wp, bcp, C_, C_);
    build_bcat_kernel<<<(C_ * FF_ + 255) / 256, 256>>>(W1, bc1, C_, FF_);
    build_bcat_kernel<<<(FF_ * C_ + 255) / 256, 256>>>(W2, bc2, FF_, C_);

    // 1. LN1 -> split acatA [hi|lo]
    ln_split_kernel<<<M_, 128>>>(x, ln1_g, ln1_b, acatA);

    // 2. fused QKV projection -> K/Q/V^T [hi|lo] bf16 directly
    mma_gemm<1><<<dim3(9, M_ / 128), 256, GEMM_SMEM>>>(
        acatA, bqkv, biasqkv, nullptr, (float*)kc, (float*)qc, (float*)vt,
        nullptr, KL1, KW1, 3 * C_);

    // 3. flash attention (writes proj input acatA directly)
    attn_mma<<<dim3(2, H_, B_), 256, ATTN2_SMEM>>>(kc, qc, vt, acatA);

    // 4. output projection + residual
    mma_gemm<4><<<dim3(3, M_ / 128), 256, GEMM_SMEM>>>(
        acatA, bcp, bp, x, x1, nullptr, nullptr, nullptr, KL1, KW1, C_);

    // 5. LN2 -> split acatA
    ln_split_kernel<<<M_, 128>>>(x1, ln2_g, ln2_b, acatA);

    // 6. FFN up + ReLU -> acat4 [hi|lo] directly
    mma_gemm<2><<<dim3(12, M_ / 128), 256, GEMM_SMEM>>>(
        acatA, bc1, b1, nullptr, nullptr, nullptr, nullptr, acat4, KL1, KW1, FF_);

    // 7. FFN down + residual -> d_out
    mma_gemm<4><<<dim3(3, M_ / 128), 256, GEMM_SMEM>>>(
        acat4, bc2, b2, x1, out, nullptr, nullptr, nullptr, KL2, KW4, C_);
}

// round 14
// speedup vs baseline: 2.1045x; 2.1045x over previous
#include <cuda_runtime.h>
#include <cuda_fp16.h>
#include <math_constants.h>
#include <cstdint>
#include <cstddef>

// Problem constants
constexpr int B_  = 128;
constexpr int T_  = 256;
constexpr int C_  = 384;
constexpr int H_  = 6;
constexpr int D_  = 64;
constexpr int FF_ = 1536;
constexpr int M_  = B_ * T_;     // 32768
constexpr int KW1 = 2 * C_;      // 768  logical/physical [hi|lo] width (attn/FFN1 A)
constexpr int KW4 = 2 * FF_;     // 3072 (FFN2 A)
constexpr int BH_ = B_ * H_;     // 768

// ---------------- scratch ----------------
__device__ __half g_acatA[(size_t)M_ * KW1];      // A [hi|lo] fp16
__device__ __half g_acat4[(size_t)M_ * KW4];      // FFN hidden [hi|lo]
__device__ __half g_bqkv [(size_t)(3 * C_) * C_]; // weights: hi only, width K0
__device__ __half g_bcp  [(size_t)C_  * C_];
__device__ __half g_bc1  [(size_t)FF_ * C_];
__device__ __half g_bc2  [(size_t)C_  * FF_];
__device__ float g_biasqkv[3 * C_];
__device__ __half g_kc[(size_t)BH_ * T_ * 128];   // K [hi|lo] along d
__device__ __half g_qc[(size_t)BH_ * T_ * 128];   // Q [hi|lo] along d
__device__ __half g_vt[(size_t)BH_ * 64 * 512];   // V^T [hi(256)|lo(256)] along s
__device__ float g_x1 [M_ * C_];

// ---------------- helpers ----------------
__device__ __forceinline__ uint32_t smem_u32(const void* p) {
    uint32_t a;
    asm("{ .reg .u64 t; cvta.to.shared.u64 t, %1; cvt.u32.u64 %0, t; }" : "=r"(a) : "l"(p));
    return a;
}
__device__ __forceinline__ void cp16(uint32_t dst, const void* src) {
    asm volatile("cp.async.cg.shared.global [%0], [%1], 16;" :: "r"(dst), "l"(src));
}
#define CP_COMMIT() asm volatile("cp.async.commit_group;" ::: "memory")
#define CP_WAIT0()  asm volatile("cp.async.wait_group 0;"  ::: "memory")
#define CP_WAIT1()  asm volatile("cp.async.wait_group 1;"  ::: "memory")
#define CP_WAIT2()  asm volatile("cp.async.wait_group 2;"  ::: "memory")

__device__ __forceinline__ void ldm_x4(uint32_t* r, uint32_t addr) {
    asm volatile("ldmatrix.sync.aligned.m8n8.x4.shared.b16 {%0,%1,%2,%3}, [%4];"
        : "=r"(r[0]), "=r"(r[1]), "=r"(r[2]), "=r"(r[3]) : "r"(addr));
}
__device__ __forceinline__ void mma16816(float* c, const uint32_t* a, uint32_t b0, uint32_t b1) {
    asm volatile("mma.sync.aligned.m16n8k16.row.col.f32.f16.f16.f32 "
        "{%0,%1,%2,%3}, {%4,%5,%6,%7}, {%8,%9}, {%0,%1,%2,%3};"
        : "+f"(c[0]), "+f"(c[1]), "+f"(c[2]), "+f"(c[3])
        : "r"(a[0]), "r"(a[1]), "r"(a[2]), "r"(a[3]), "r"(b0), "r"(b1));
}
__device__ __forceinline__ void split2(float v, __half& hi, __half& lo) {
    hi = __float2half(v);
    lo = __float2half(v - __half2float(hi));
}
__device__ __forceinline__ uint32_t pack2(__half a, __half b) {
    __half2 p = __halves2half2(a, b);
    return *(uint32_t*)&p;
}

// ---------------- LayerNorm -> split activation [hi|lo] ----------------
__global__ void ln_split_kernel(const float* __restrict__ x, const float* __restrict__ g,
                                const float* __restrict__ b, __half* __restrict__ acat)
{
    int row = blockIdx.x;
    const float* xr = x + (size_t)row * C_;
    int tid = threadIdx.x;
    float v0 = xr[tid], v1 = xr[tid + 128], v2 = xr[tid + 256];
    float s  = v0 + v1 + v2;
    float sq = v0 * v0 + v1 * v1 + v2 * v2;
    #pragma unroll
    for (int o = 16; o; o >>= 1) {
        s  += __shfl_xor_sync(0xffffffffu, s,  o);
        sq += __shfl_xor_sync(0xffffffffu, sq, o);
    }
    __shared__ float red[2][4];
    int wid = tid >> 5, lane = tid & 31;
    if (lane == 0) { red[0][wid] = s; red[1][wid] = sq; }
    __syncthreads();
    s  = red[0][0] + red[0][1] + red[0][2] + red[0][3];
    sq = red[1][0] + red[1][1] + red[1][2] + red[1][3];
    float mu  = s * (1.0f / C_);
    float var = sq * (1.0f / C_) - mu * mu;
    float inv = rsqrtf(var + 1e-5f);
    __half* orow = acat + (size_t)row * KW1;
    #pragma unroll
    for (int u = 0; u < 3; u++) {
        int k = tid + u * 128;
        float vv = (u == 0 ? v0 : (u == 1 ? v1 : v2));
        float y = (vv - mu) * inv * g[k] + b[k];
        __half hi, lo; split2(y, hi, lo);
        orow[k] = hi; orow[C_ + k] = lo;
    }
}

// ---------------- weight builders: hi only, [n][k] width K ----------------
__global__ void build_bh_kernel(const float* __restrict__ W, __half* __restrict__ Bh,
                                int K, int N)
{
    size_t idx = (size_t)blockIdx.x * 256 + threadIdx.x;
    if (idx >= (size_t)K * N) return;
    int n = (int)(idx / K);
    int k = (int)(idx % K);
    Bh[(size_t)n * K + k] = __float2half(W[(size_t)k * N + n]);
}

__global__ void build_bh_qkv_kernel(const float* __restrict__ Wk, const float* __restrict__ Wq,
                                    const float* __restrict__ Wv, __half* __restrict__ Bh)
{
    size_t idx = (size_t)blockIdx.x * 256 + threadIdx.x;
    if (idx >= (size_t)(3 * C_) * C_) return;
    int n = (int)(idx / C_);
    int k = (int)(idx % C_);
    int sel = n / C_;
    int nn = n - sel * C_;
    int h = nn >> 6, d = nn & 63;
    const float* Ws = (sel == 0) ? Wk : (sel == 1) ? Wq : Wv;
    Bh[(size_t)n * C_ + k] = __float2half(Ws[((size_t)h * C_ + k) * 64 + d]);
}

__global__ void bias_concat_kernel(const float* __restrict__ bk, const float* __restrict__ bq,
                                   const float* __restrict__ bv, float* __restrict__ out)
{
    int t = blockIdx.x * 256 + threadIdx.x;
    if (t >= 3 * C_) return;
    int sel = t / C_, nn = t % C_;
    out[t] = (sel == 0 ? bk : sel == 1 ? bq : bv)[nn];
}

// ---------------- mma.sync GEMM: 128x128, BK=32, 4-stage async pipeline -------
// A phys [hi|lo] width Klog (= logical, no remap). B phys hi-only width Bw = Klog/2;
// logical B = [hi|hi] via chunk remap. 80KB smem, 2 CTAs/SM.
constexpr uint32_t G_ASTG = 128u * 80;        // 10240 bytes per stage (one operand)
constexpr uint32_t G_BOFF = 4u * G_ASTG;      // B region offset
constexpr int GEMM_SMEM = (int)(8u * G_ASTG); // 81920

template<int FLAGS>
__global__ void __launch_bounds__(256)
mma_gemm(const __half* __restrict__ A, const __half* __restrict__ Bc,
         const float* __restrict__ bias, const float* __restrict__ resid,
         float* __restrict__ out0, float* __restrict__ out1, float* __restrict__ out2,
         __half* __restrict__ acat_out, int Klog, int Bw, int N)
{
    extern __shared__ char gsm[];
    uint32_t sb = smem_u32(gsm);

    int tid  = threadIdx.x;
    int wid  = tid >> 5;
    int lane = tid & 31;
    int wm = wid >> 2;
    int wn = wid & 3;
    int m0 = blockIdx.y * 128;
    int n0 = blockIdx.x * 128;
    int NC = Klog / 32;
    int KB = Bw / 32;              // B chunks in hi region

    int lrow = tid >> 2;
    int lseg = tid & 3;
    const __half* aBase0 = A  + (size_t)(m0 + lrow)      * Klog + lseg * 8;
    const __half* aBase1 = A  + (size_t)(m0 + lrow + 64) * Klog + lseg * 8;
    const __half* bBase0 = Bc + (size_t)(n0 + lrow)      * Bw + lseg * 8;
    const __half* bBase1 = Bc + (size_t)(n0 + lrow + 64) * Bw + lseg * 8;

    uint32_t dA0 = sb + lrow * 80 + lseg * 16;
    uint32_t dA1 = dA0 + 64 * 80;
    uint32_t dB0 = dA0 + G_BOFF;
    uint32_t dB1 = dA1 + G_BOFF;

    auto load_chunk = [&](int c, int st) {
        int pc = (c < KB) ? c : c - KB;    // B logical [hi|hi]
        uint32_t o = (uint32_t)st * G_ASTG;
        cp16(dA0 + o, aBase0 + (size_t)c * 32);
        cp16(dA1 + o, aBase1 + (size_t)c * 32);
        cp16(dB0 + o, bBase0 + (size_t)pc * 32);
        cp16(dB1 + o, bBase1 + (size_t)pc * 32);
    };

    int q = lane >> 3, i = lane & 7;
    uint32_t aOff = sb + (wm * 64 + (q & 1) * 8 + i) * 80 + (q >> 1) * 16;
    uint32_t bOff = sb + G_BOFF + (wn * 32 + (q >> 1) * 8 + i) * 80 + (q & 1) * 16;

    float acc[4][4][4];
    #pragma unroll
    for (int mt = 0; mt < 4; mt++)
        #pragma unroll
        for (int nt = 0; nt < 4; nt++)
            #pragma unroll
            for (int r = 0; r < 4; r++) acc[mt][nt][r] = 0.0f;

    #pragma unroll
    for (int s = 0; s < 3; s++) { load_chunk(s, s); CP_COMMIT(); }

    for (int c = 0; c < NC; c++) {
        int st = c & 3;
        CP_WAIT2();
        __syncthreads();
        if (c + 3 < NC) load_chunk(c + 3, (c + 3) & 3);
        CP_COMMIT();

        uint32_t aS = aOff + (uint32_t)st * G_ASTG;
        uint32_t bS = bOff + (uint32_t)st * G_ASTG;
        #pragma unroll
        for (int ks = 0; ks < 2; ks++) {
            uint32_t af[4][4], bf[2][4];
            #pragma unroll
            for (int mt = 0; mt < 4; mt++)
                ldm_x4(af[mt], aS + mt * 16 * 80 + ks * 32);
            #pragma unroll
            for (int p = 0; p < 2; p++)
                ldm_x4(bf[p], bS + p * 16 * 80 + ks * 32);
            #pragma unroll
            for (int mt = 0; mt < 4; mt++)
                #pragma unroll
                for (int nt = 0; nt < 4; nt++)
                    mma16816(acc[mt][nt], af[mt], bf[nt >> 1][(nt & 1) * 2],
                             bf[nt >> 1][(nt & 1) * 2 + 1]);
        }
    }

    // ---------------- epilogue ----------------
    int mrow = lane >> 2;
    int ncl  = (lane & 3) * 2;
    #pragma unroll
    for (int mt = 0; mt < 4; mt++) {
        #pragma unroll
        for (int half = 0; half < 2; half++) {
            int m = m0 + wm * 64 + mt * 16 + mrow + half * 8;
            #pragma unroll
            for (int nt = 0; nt < 4; nt++) {
                int n = n0 + wn * 32 + nt * 8 + ncl;
                float v0 = acc[mt][nt][half * 2 + 0] + bias[n];
                float v1 = acc[mt][nt][half * 2 + 1] + bias[n + 1];
                if (FLAGS == 1) {
                    int sel = n / C_;
                    int nn = n - sel * C_;
                    int b_ = m >> 8, t = m & 255;
                    int hh = nn >> 6, d0 = nn & 63;
                    int bh = b_ * H_ + hh;
                    __half h0, l0, h1, l1;
                    split2(v0, h0, l0); split2(v1, h1, l1);
                    if (sel == 0) {                     // K [hi|lo], width 128
                        __half* p = (__half*)out0 + ((size_t)bh * T_ + t) * 128 + d0;
                        *(uint32_t*)(p)      = pack2(h0, h1);
                        *(uint32_t*)(p + 64) = pack2(l0, l1);
                    } else if (sel == 1) {              // Q [hi|lo], width 128
                        __half* p = (__half*)out1 + ((size_t)bh * T_ + t) * 128 + d0;
                        *(uint32_t*)(p)      = pack2(h0, h1);
                        *(uint32_t*)(p + 64) = pack2(l0, l1);
                    } else {                            // V^T [hi|lo] along s, width 512
                        __half* p0 = (__half*)out2 + ((size_t)bh * 64 + d0) * 512 + t;
                        p0[0] = h0; p0[256] = l0;
                        __half* p1 = p0 + 512;
                        p1[0] = h1; p1[256] = l1;
                    }
                } else if (FLAGS == 2) {
                    v0 = fmaxf(v0, 0.0f); v1 = fmaxf(v1, 0.0f);
                    __half h0, l0, h1, l1;
                    split2(v0, h0, l0); split2(v1, h1, l1);
                    __half* rowp = acat_out + (size_t)m * KW4 + n;
                    *(uint32_t*)(rowp)       = pack2(h0, h1);
                    *(uint32_t*)(rowp + FF_) = pack2(l0, l1);
                } else {
                    if (FLAGS & 4) {
                        const float2 rv = *(const float2*)(resid + (size_t)m * N + n);
                        v0 += rv.x; v1 += rv.y;
                    }
                    *(float2*)(out0 + (size_t)m * N + n) = make_float2(v0, v1);
                }
            }
        }
    }
}

// ---------------- flash attention: fp16 2-term, double-buffered Q/V ------------
// S = (Khi+Klo).Qhi : k'=128, A phys identity, B remap [hi|hi]
// O = (Phi+Plo).Vhi : same structure. stride 272B rows, ~136KB smem.
constexpr uint32_t AOFF_K = 0;                          // 128 rows
constexpr uint32_t AQSTG  = 64u * 272;                  // 17408 per stage
constexpr uint32_t AOFF_Q = 128u * 272;                 // 34816 (2 stages)
constexpr uint32_t AOFF_V = AOFF_Q + 2 * AQSTG;         // 69632 (2 stages)
constexpr uint32_t AOFF_P = AOFF_V + 2 * AQSTG;         // 104448 (128 rows)
constexpr int ATTN2_SMEM = (int)(AOFF_P + 128u * 272);  // 139264

__global__ void __launch_bounds__(256)
attn_mma(const __half* __restrict__ Kc, const __half* __restrict__ Qc,
         const __half* __restrict__ Vt, __half* __restrict__ acat)
{
    extern __shared__ char smb[];
    uint32_t sb = smem_u32(smb);
    int tid = threadIdx.x, wid = tid >> 5, lane = tid & 31;
    int tt = blockIdx.x, h = blockIdx.y, b = blockIdx.z;
    int bh = b * H_ + h;
    const __half* Kg = Kc + ((size_t)bh * T_ + (size_t)tt * 128) * 128;
    const __half* Qg = Qc + (size_t)bh * T_ * 128;
    const __half* Vg = Vt + (size_t)bh * 64 * 512;

    // K tile: 128 rows x 16 chunks (phys [hi|lo] 128 cols)
    #pragma unroll
    for (int it = 0; it < 8; it++) {
        int ch = tid + it * 256;
        int r = ch >> 4, c = ch & 15;
        cp16(sb + AOFF_K + r * 272 + c * 16, Kg + (size_t)r * 128 + c * 8);
    }
    CP_COMMIT();

    int nst = tt * 2 + 2;
    auto loadQV = [&](int st) {
        int stg = st & 1;
        const __half* Qt = Qg + (size_t)st * 64 * 128;
        // Q: hi only (64 cols = 8 chunks) per 64 rows
        #pragma unroll
        for (int it = 0; it < 2; it++) {
            int ch = tid + it * 256;
            int r = ch >> 3, c = ch & 7;
            cp16(sb + AOFF_Q + stg * AQSTG + r * 272 + c * 16, Qt + (size_t)r * 128 + c * 8);
        }
        // V: hi only (64 cols of this stage from hi region [0,256))
        #pragma unroll
        for (int it = 0; it < 2; it++) {
            int ch = tid + it * 256;
            int r = ch >> 3, c = ch & 7;
            int gcol = st * 64 + c * 8;
            cp16(sb + AOFF_V + stg * AQSTG + r * 272 + c * 16, Vg + (size_t)r * 512 + gcol);
        }
        CP_COMMIT();
    };
    loadQV(0);

    float m_run[2] = { -CUDART_INF_F, -CUDART_INF_F };
    float l_run[2] = { 0.0f, 0.0f };
    float oacc[8][4];
    #pragma unroll
    for (int nt = 0; nt < 8; nt++)
        #pragma unroll
        for (int e = 0; e < 4; e++) oacc[nt][e] = 0.0f;

    const float scl = rsqrtf((float)C_);
    int q = lane >> 3, i5 = lane & 7;
    uint32_t aK = sb + AOFF_K + (wid * 16 + (q & 1) * 8 + i5) * 272 + (q >> 1) * 16;
    uint32_t aP = sb + AOFF_P + (wid * 16 + (q & 1) * 8 + i5) * 272 + (q >> 1) * 16;
    uint32_t bQ = sb + AOFF_Q + ((q >> 1) * 8 + i5) * 272 + (q & 1) * 16;
    uint32_t bV = sb + AOFF_V + ((q >> 1) * 8 + i5) * 272 + (q & 1) * 16;

    int r0 = lane >> 2;
    int tg0 = tt * 128 + wid * 16 + r0;
    int tg1 = tg0 + 8;
    __half* sP = (__half*)(smb + AOFF_P);

    for (int st = 0; st < nst; st++) {
        int stg = st & 1;
        if (st + 1 < nst) { loadQV(st + 1); CP_WAIT1(); } else { CP_WAIT0(); }
        __syncthreads();

        // S = K.Q : k'=128 (8 steps); A identity [hi|lo], B remap [hi|hi]
        float sacc[8][4];
        #pragma unroll
        for (int nt = 0; nt < 8; nt++)
            #pragma unroll
            for (int e = 0; e < 4; e++) sacc[nt][e] = 0.0f;
        #pragma unroll
        for (int ks = 0; ks < 8; ks++) {
            int kb = ks & 3;                      // Q hi only
            uint32_t af[4], bf[4][4];
            ldm_x4(af, aK + ks * 32);
            #pragma unroll
            for (int p = 0; p < 4; p++)
                ldm_x4(bf[p], bQ + stg * AQSTG + p * 16 * 272 + kb * 32);
            #pragma unroll
            for (int nt = 0; nt < 8; nt++)
                mma16816(sacc[nt], af, bf[nt >> 1][(nt & 1) * 2],
                         bf[nt >> 1][(nt & 1) * 2 + 1]);
        }

        float mx0 = -CUDART_INF_F, mx1 = -CUDART_INF_F;
        #pragma unroll
        for (int nt = 0; nt < 8; nt++) {
            #pragma unroll
            for (int e = 0; e < 2; e++) {
                int sg = st * 64 + nt * 8 + (lane & 3) * 2 + e;
                float v0 = sacc[nt][e] * scl;
                if (sg > tg0) v0 = -CUDART_INF_F;
                sacc[nt][e] = v0; mx0 = fmaxf(mx0, v0);
                float v1 = sacc[nt][2 + e] * scl;
                if (sg > tg1) v1 = -CUDART_INF_F;
                sacc[nt][2 + e] = v1; mx1 = fmaxf(mx1, v1);
            }
        }
        mx0 = fmaxf(mx0, __shfl_xor_sync(0xffffffffu, mx0, 1));
        mx0 = fmaxf(mx0, __shfl_xor_sync(0xffffffffu, mx0, 2));
        mx1 = fmaxf(mx1, __shfl_xor_sync(0xffffffffu, mx1, 1));
        mx1 = fmaxf(mx1, __shfl_xor_sync(0xffffffffu, mx1, 2));

        float mn0 = fmaxf(m_run[0], mx0), mn1 = fmaxf(m_run[1], mx1);
        float es0 = __expf(m_run[0] - mn0), es1 = __expf(m_run[1] - mn1);
        m_run[0] = mn0; m_run[1] = mn1;

        float sum0 = 0.0f, sum1 = 0.0f;
        #pragma unroll
        for (int nt = 0; nt < 8; nt++) {
            #pragma unroll
            for (int e = 0; e < 2; e++) {
                float p0 = __expf(sacc[nt][e] - mn0);     sacc[nt][e] = p0;     sum0 += p0;
                float p1 = __expf(sacc[nt][2 + e] - mn1); sacc[nt][2 + e] = p1; sum1 += p1;
            }
        }
        sum0 += __shfl_xor_sync(0xffffffffu, sum0, 1);
        sum0 += __shfl_xor_sync(0xffffffffu, sum0, 2);
        sum1 += __shfl_xor_sync(0xffffffffu, sum1, 1);
        sum1 += __shfl_xor_sync(0xffffffffu, sum1, 2);
        l_run[0] = l_run[0] * es0 + sum0;
        l_run[1] = l_run[1] * es1 + sum1;

        #pragma unroll
        for (int nt = 0; nt < 8; nt++) {
            oacc[nt][0] *= es0; oacc[nt][1] *= es0;
            oacc[nt][2] *= es1; oacc[nt][3] *= es1;
        }

        // write P phys [hi|lo] (136 fp16 row stride)
        #pragma unroll
        for (int nt = 0; nt < 8; nt++) {
            int cb = nt * 8 + (lane & 3) * 2;
            __half h0, l0, h1, l1;
            split2(sacc[nt][0], h0, l0); split2(sacc[nt][1], h1, l1);
            __half* pr = sP + (wid * 16 + r0) * 136 + cb;
            *(uint32_t*)(pr)      = pack2(h0, h1);
            *(uint32_t*)(pr + 64) = pack2(l0, l1);
            split2(sacc[nt][2], h0, l0); split2(sacc[nt][3], h1, l1);
            __half* pr2 = pr + 8 * 136;
            *(uint32_t*)(pr2)      = pack2(h0, h1);
            *(uint32_t*)(pr2 + 64) = pack2(l0, l1);
        }
        __syncthreads();

        // O += P.V : k'=128 (8 steps); A identity [Phi|Plo], B remap [Vhi|Vhi]
        #pragma unroll
        for (int ks = 0; ks < 8; ks++) {
            int kb = ks & 3;
            uint32_t af[4], bf[4][4];
            ldm_x4(af, aP + ks * 32);
            #pragma unroll
            for (int p = 0; p < 4; p++)
                ldm_x4(bf[p], bV + stg * AQSTG + p * 16 * 272 + kb * 32);
            #pragma unroll
            for (int nt = 0; nt < 8; nt++)
                mma16816(oacc[nt], af, bf[nt >> 1][(nt & 1) * 2],
                         bf[nt >> 1][(nt & 1) * 2 + 1]);
        }
        __syncthreads();
    }

    // epilogue: normalize, split, write acatA [hi|lo] rows directly
    float inv0 = 1.0f / l_run[0], inv1 = 1.0f / l_run[1];
    int t0 = tt * 128 + wid * 16 + r0;
    size_t mrow0 = (size_t)(b * T_ + t0) * KW1;
    size_t mrow1 = mrow0 + (size_t)8 * KW1;
    #pragma unroll
    for (int nt = 0; nt < 8; nt++) {
        int k = h * 64 + nt * 8 + (lane & 3) * 2;
        {
            float v0 = oacc[nt][0] * inv0, v1 = oacc[nt][1] * inv0;
            __half h0, l0, h1, l1;
            split2(v0, h0, l0); split2(v1, h1, l1);
            __half* p = g_acatA + mrow0 + k;
            *(uint32_t*)(p)      = pack2(h0, h1);
            *(uint32_t*)(p + C_) = pack2(l0, l1);
        }
        {
            float v0 = oacc[nt][2] * inv1, v1 = oacc[nt][3] * inv1;
            __half h0, l0, h1, l1;
            split2(v0, h0, l0); split2(v1, h1, l1);
            __half* p = g_acatA + mrow1 + k;
            *(uint32_t*)(p)      = pack2(h0, h1);
            *(uint32_t*)(p + C_) = pack2(l0, l1);
        }
    }
}

// ---------------- host orchestration -------------------------------------------
extern "C" void kernel_launch(void* const* d_in, const int* in_sizes, int n_in,
                              void* d_out, int out_size)
{
    const float* x     = (const float*)d_in[0];
    const float* ln1_g = (const float*)d_in[1];
    const float* ln1_b = (const float*)d_in[2];
    const float* Wk    = (const float*)d_in[3];
    const float* bk    = (const float*)d_in[4];
    const float* Wq    = (const float*)d_in[5];
    const float* bq    = (const float*)d_in[6];
    const float* Wv    = (const float*)d_in[7];
    const float* bv    = (const float*)d_in[8];
    const float* Wp    = (const float*)d_in[9];
    const float* bp    = (const float*)d_in[10];
    const float* ln2_g = (const float*)d_in[11];
    const float* ln2_b = (const float*)d_in[12];
    const float* W1    = (const float*)d_in[13];
    const float* b1    = (const float*)d_in[14];
    const float* W2    = (const float*)d_in[15];
    const float* b2    = (const float*)d_in[16];
    float* out = (float*)d_out;

    __half *acatA, *acat4, *bqkv, *bcp, *bc1, *bc2, *kc, *qc, *vt;
    float *biasqkv, *x1;
    cudaGetSymbolAddress((void**)&acatA,   g_acatA);
    cudaGetSymbolAddress((void**)&acat4,   g_acat4);
    cudaGetSymbolAddress((void**)&bqkv,    g_bqkv);
    cudaGetSymbolAddress((void**)&bcp,     g_bcp);
    cudaGetSymbolAddress((void**)&bc1,     g_bc1);
    cudaGetSymbolAddress((void**)&bc2,     g_bc2);
    cudaGetSymbolAddress((void**)&biasqkv, g_biasqkv);
    cudaGetSymbolAddress((void**)&kc,  g_kc);
    cudaGetSymbolAddress((void**)&qc,  g_qc);
    cudaGetSymbolAddress((void**)&vt,  g_vt);
    cudaGetSymbolAddress((void**)&x1,  g_x1);

    cudaFuncSetAttribute(attn_mma, cudaFuncAttributeMaxDynamicSharedMemorySize, ATTN2_SMEM);
    cudaFuncSetAttribute(mma_gemm<1>, cudaFuncAttributeMaxDynamicSharedMemorySize, GEMM_SMEM);
    cudaFuncSetAttribute(mma_gemm<2>, cudaFuncAttributeMaxDynamicSharedMemorySize, GEMM_SMEM);
    cudaFuncSetAttribute(mma_gemm<4>, cudaFuncAttributeMaxDynamicSharedMemorySize, GEMM_SMEM);

    // weight / bias conversions (hi-only fp16)
    bias_concat_kernel<<<5, 256>>>(bk, bq, bv, biasqkv);
    build_bh_qkv_kernel<<<(3 * C_ * C_ + 255) / 256, 256>>>(Wk, Wq, Wv, bqkv);
    build_bh_kernel<<<(C_ * C_ + 255) / 256, 256>>>(Wp, bcp, C_, C_);
    build_bh_kernel<<<(C_ * FF_ + 255) / 256, 256>>>(W1, bc1, C_, FF_);
    build_bh_kernel<<<(FF_ * C_ + 255) / 256, 256>>>(W2, bc2, FF_, C_);

    // 1. LN1 -> split acatA [hi|lo]
    ln_split_kernel<<<M_, 128>>>(x, ln1_g, ln1_b, acatA);

    // 2. fused QKV projection (Klog=768, Bw=384, N=1152)
    mma_gemm<1><<<dim3(9, M_ / 128), 256, GEMM_SMEM>>>(
        acatA, bqkv, biasqkv, nullptr, (float*)kc, (float*)qc, (float*)vt,
        nullptr, KW1, C_, 3 * C_);

    // 3. flash attention (writes proj input acatA directly)
    attn_mma<<<dim3(2, H_, B_), 256, ATTN2_SMEM>>>(kc, qc, vt, acatA);

    // 4. output projection + residual (Klog=768, Bw=384, N=384)
    mma_gemm<4><<<dim3(3, M_ / 128), 256, GEMM_SMEM>>>(
        acatA, bcp, bp, x, x1, nullptr, nullptr, nullptr, KW1, C_, C_);

    // 5. LN2 -> split acatA
    ln_split_kernel<<<M_, 128>>>(x1, ln2_g, ln2_b, acatA);

    // 6. FFN up + ReLU -> acat4 [hi|lo] (Klog=768, Bw=384, N=1536)
    mma_gemm<2><<<dim3(12, M_ / 128), 256, GEMM_SMEM>>>(
        acatA, bc1, b1, nullptr, nullptr, nullptr, nullptr, acat4, KW1, C_, FF_);

    // 7. FFN down + residual -> d_out (Klog=3072, Bw=1536, N=384)
    mma_gemm<4><<<dim3(3, M_ / 128), 256, GEMM_SMEM>>>(
        acat4, bc2, b2, x1, out, nullptr, nullptr, nullptr, KW4, FF_, C_);
}

// round 15
// speedup vs baseline: 3.8461x; 1.8276x over previous
#include <cuda_runtime.h>
#include <cuda_fp16.h>
#include <math_constants.h>
#include <cstdint>
#include <cstddef>

// Problem constants
constexpr int B_  = 128;
constexpr int T_  = 256;
constexpr int C_  = 384;
constexpr int H_  = 6;
constexpr int D_  = 64;
constexpr int FF_ = 1536;
constexpr int M_  = B_ * T_;     // 32768
constexpr int BH_ = B_ * H_;     // 768

// ---------------- scratch (pure fp16, no hi/lo planes) ----------------
__device__ __half g_acatA[(size_t)M_ * C_];       // activations fp16
__device__ __half g_acat4[(size_t)M_ * FF_];      // FFN hidden fp16
__device__ __half g_bqkv [(size_t)(3 * C_) * C_]; // weights [n][k]
__device__ __half g_bcp  [(size_t)C_  * C_];
__device__ __half g_bc1  [(size_t)FF_ * C_];
__device__ __half g_bc2  [(size_t)C_  * FF_];
__device__ float g_biasqkv[3 * C_];
__device__ __half g_kc[(size_t)BH_ * T_ * 64];    // K (bh,t,d)
__device__ __half g_qc[(size_t)BH_ * T_ * 64];    // Q (bh,t,d)
__device__ __half g_vt[(size_t)BH_ * 64 * 256];   // V^T (bh,d,s)
__device__ float g_x1 [M_ * C_];

// ---------------- helpers ----------------
__device__ __forceinline__ uint32_t smem_u32(const void* p) {
    uint32_t a;
    asm("{ .reg .u64 t; cvta.to.shared.u64 t, %1; cvt.u32.u64 %0, t; }" : "=r"(a) : "l"(p));
    return a;
}
__device__ __forceinline__ void cp16(uint32_t dst, const void* src) {
    asm volatile("cp.async.cg.shared.global [%0], [%1], 16;" :: "r"(dst), "l"(src));
}
#define CP_COMMIT() asm volatile("cp.async.commit_group;" ::: "memory")
#define CP_WAIT0()  asm volatile("cp.async.wait_group 0;"  ::: "memory")
#define CP_WAIT1()  asm volatile("cp.async.wait_group 1;"  ::: "memory")
#define CP_WAIT2()  asm volatile("cp.async.wait_group 2;"  ::: "memory")

__device__ __forceinline__ void ldm_x4(uint32_t* r, uint32_t addr) {
    asm volatile("ldmatrix.sync.aligned.m8n8.x4.shared.b16 {%0,%1,%2,%3}, [%4];"
        : "=r"(r[0]), "=r"(r[1]), "=r"(r[2]), "=r"(r[3]) : "r"(addr));
}
__device__ __forceinline__ void mma16816(float* c, const uint32_t* a, uint32_t b0, uint32_t b1) {
    asm volatile("mma.sync.aligned.m16n8k16.row.col.f32.f16.f16.f32 "
        "{%0,%1,%2,%3}, {%4,%5,%6,%7}, {%8,%9}, {%0,%1,%2,%3};"
        : "+f"(c[0]), "+f"(c[1]), "+f"(c[2]), "+f"(c[3])
        : "r"(a[0]), "r"(a[1]), "r"(a[2]), "r"(a[3]), "r"(b0), "r"(b1));
}
__device__ __forceinline__ uint32_t pack2f(float a, float b) {
    __half2 p = __halves2half2(__float2half(a), __float2half(b));
    return *(uint32_t*)&p;
}

// ---------------- LayerNorm -> fp16 activations ----------------
__global__ void ln_h_kernel(const float* __restrict__ x, const float* __restrict__ g,
                            const float* __restrict__ b, __half* __restrict__ acat)
{
    int row = blockIdx.x;
    const float* xr = x + (size_t)row * C_;
    int tid = threadIdx.x;
    float v0 = xr[tid], v1 = xr[tid + 128], v2 = xr[tid + 256];
    float s  = v0 + v1 + v2;
    float sq = v0 * v0 + v1 * v1 + v2 * v2;
    #pragma unroll
    for (int o = 16; o; o >>= 1) {
        s  += __shfl_xor_sync(0xffffffffu, s,  o);
        sq += __shfl_xor_sync(0xffffffffu, sq, o);
    }
    __shared__ float red[2][4];
    int wid = tid >> 5, lane = tid & 31;
    if (lane == 0) { red[0][wid] = s; red[1][wid] = sq; }
    __syncthreads();
    s  = red[0][0] + red[0][1] + red[0][2] + red[0][3];
    sq = red[1][0] + red[1][1] + red[1][2] + red[1][3];
    float mu  = s * (1.0f / C_);
    float var = sq * (1.0f / C_) - mu * mu;
    float inv = rsqrtf(var + 1e-5f);
    __half* orow = acat + (size_t)row * C_;
    #pragma unroll
    for (int u = 0; u < 3; u++) {
        int k = tid + u * 128;
        float vv = (u == 0 ? v0 : (u == 1 ? v1 : v2));
        orow[k] = __float2half((vv - mu) * inv * g[k] + b[k]);
    }
}

// ---------------- weight builders ----------------
__global__ void build_bh_kernel(const float* __restrict__ W, __half* __restrict__ Bh,
                                int K, int N)
{
    size_t idx = (size_t)blockIdx.x * 256 + threadIdx.x;
    if (idx >= (size_t)K * N) return;
    int n = (int)(idx / K);
    int k = (int)(idx % K);
    Bh[(size_t)n * K + k] = __float2half(W[(size_t)k * N + n]);
}

__global__ void build_bh_qkv_kernel(const float* __restrict__ Wk, const float* __restrict__ Wq,
                                    const float* __restrict__ Wv, __half* __restrict__ Bh)
{
    size_t idx = (size_t)blockIdx.x * 256 + threadIdx.x;
    if (idx >= (size_t)(3 * C_) * C_) return;
    int n = (int)(idx / C_);
    int k = (int)(idx % C_);
    int sel = n / C_;
    int nn = n - sel * C_;
    int h = nn >> 6, d = nn & 63;
    const float* Ws = (sel == 0) ? Wk : (sel == 1) ? Wq : Wv;
    Bh[(size_t)n * C_ + k] = __float2half(Ws[((size_t)h * C_ + k) * 64 + d]);
}

__global__ void bias_concat_kernel(const float* __restrict__ bk, const float* __restrict__ bq,
                                   const float* __restrict__ bv, float* __restrict__ out)
{
    int t = blockIdx.x * 256 + threadIdx.x;
    if (t >= 3 * C_) return;
    int sel = t / C_, nn = t % C_;
    out[t] = (sel == 0 ? bk : sel == 1 ? bq : bv)[nn];
}

// ---------------- mma.sync GEMM: 128x128, BK=32, 4-stage async pipeline -------
// Pure fp16, no remaps. 80KB smem, 2 CTAs/SM.
constexpr uint32_t G_ASTG = 128u * 80;        // 10240 bytes per stage (one operand)
constexpr uint32_t G_BOFF = 4u * G_ASTG;      // B region offset
constexpr int GEMM_SMEM = (int)(8u * G_ASTG); // 81920

template<int FLAGS>
__global__ void __launch_bounds__(256)
mma_gemm(const __half* __restrict__ A, const __half* __restrict__ Bc,
         const float* __restrict__ bias, const float* __restrict__ resid,
         float* __restrict__ out0, float* __restrict__ out1, float* __restrict__ out2,
         __half* __restrict__ acat_out, int K, int N)
{
    extern __shared__ char gsm[];
    uint32_t sb = smem_u32(gsm);

    int tid  = threadIdx.x;
    int wid  = tid >> 5;
    int lane = tid & 31;
    int wm = wid >> 2;
    int wn = wid & 3;
    int m0 = blockIdx.y * 128;
    int n0 = blockIdx.x * 128;
    int NC = K / 32;

    int lrow = tid >> 2;
    int lseg = tid & 3;
    const __half* aBase0 = A  + (size_t)(m0 + lrow)      * K + lseg * 8;
    const __half* aBase1 = A  + (size_t)(m0 + lrow + 64) * K + lseg * 8;
    const __half* bBase0 = Bc + (size_t)(n0 + lrow)      * K + lseg * 8;
    const __half* bBase1 = Bc + (size_t)(n0 + lrow + 64) * K + lseg * 8;

    uint32_t dA0 = sb + lrow * 80 + lseg * 16;
    uint32_t dA1 = dA0 + 64 * 80;
    uint32_t dB0 = dA0 + G_BOFF;
    uint32_t dB1 = dA1 + G_BOFF;

    auto load_chunk = [&](int c, int st) {
        uint32_t o = (uint32_t)st * G_ASTG;
        cp16(dA0 + o, aBase0 + (size_t)c * 32);
        cp16(dA1 + o, aBase1 + (size_t)c * 32);
        cp16(dB0 + o, bBase0 + (size_t)c * 32);
        cp16(dB1 + o, bBase1 + (size_t)c * 32);
    };

    int q = lane >> 3, i = lane & 7;
    uint32_t aOff = sb + (wm * 64 + (q & 1) * 8 + i) * 80 + (q >> 1) * 16;
    uint32_t bOff = sb + G_BOFF + (wn * 32 + (q >> 1) * 8 + i) * 80 + (q & 1) * 16;

    float acc[4][4][4];
    #pragma unroll
    for (int mt = 0; mt < 4; mt++)
        #pragma unroll
        for (int nt = 0; nt < 4; nt++)
            #pragma unroll
            for (int r = 0; r < 4; r++) acc[mt][nt][r] = 0.0f;

    #pragma unroll
    for (int s = 0; s < 3; s++) { load_chunk(s, s); CP_COMMIT(); }

    for (int c = 0; c < NC; c++) {
        int st = c & 3;
        CP_WAIT2();
        __syncthreads();
        if (c + 3 < NC) load_chunk(c + 3, (c + 3) & 3);
        CP_COMMIT();

        uint32_t aS = aOff + (uint32_t)st * G_ASTG;
        uint32_t bS = bOff + (uint32_t)st * G_ASTG;
        #pragma unroll
        for (int ks = 0; ks < 2; ks++) {
            uint32_t af[4][4], bf[2][4];
            #pragma unroll
            for (int mt = 0; mt < 4; mt++)
                ldm_x4(af[mt], aS + mt * 16 * 80 + ks * 32);
            #pragma unroll
            for (int p = 0; p < 2; p++)
                ldm_x4(bf[p], bS + p * 16 * 80 + ks * 32);
            #pragma unroll
            for (int mt = 0; mt < 4; mt++)
                #pragma unroll
                for (int nt = 0; nt < 4; nt++)
                    mma16816(acc[mt][nt], af[mt], bf[nt >> 1][(nt & 1) * 2],
                             bf[nt >> 1][(nt & 1) * 2 + 1]);
        }
    }

    // ---------------- epilogue ----------------
    int mrow = lane >> 2;
    int ncl  = (lane & 3) * 2;
    #pragma unroll
    for (int mt = 0; mt < 4; mt++) {
        #pragma unroll
        for (int half = 0; half < 2; half++) {
            int m = m0 + wm * 64 + mt * 16 + mrow + half * 8;
            #pragma unroll
            for (int nt = 0; nt < 4; nt++) {
                int n = n0 + wn * 32 + nt * 8 + ncl;
                float v0 = acc[mt][nt][half * 2 + 0] + bias[n];
                float v1 = acc[mt][nt][half * 2 + 1] + bias[n + 1];
                if (FLAGS == 1) {
                    int sel = n / C_;
                    int nn = n - sel * C_;
                    int b_ = m >> 8, t = m & 255;
                    int hh = nn >> 6, d0 = nn & 63;
                    int bh = b_ * H_ + hh;
                    if (sel == 0) {                     // K, width 64
                        __half* p = (__half*)out0 + ((size_t)bh * T_ + t) * 64 + d0;
                        *(uint32_t*)(p) = pack2f(v0, v1);
                    } else if (sel == 1) {              // Q, width 64
                        __half* p = (__half*)out1 + ((size_t)bh * T_ + t) * 64 + d0;
                        *(uint32_t*)(p) = pack2f(v0, v1);
                    } else {                            // V^T, width 256 along s
                        __half* p0 = (__half*)out2 + ((size_t)bh * 64 + d0) * 256 + t;
                        p0[0]   = __float2half(v0);
                        p0[256] = __float2half(v1);
                    }
                } else if (FLAGS == 2) {
                    v0 = fmaxf(v0, 0.0f); v1 = fmaxf(v1, 0.0f);
                    __half* rowp = acat_out + (size_t)m * FF_ + n;
                    *(uint32_t*)(rowp) = pack2f(v0, v1);
                } else {
                    if (FLAGS & 4) {
                        const float2 rv = *(const float2*)(resid + (size_t)m * N + n);
                        v0 += rv.x; v1 += rv.y;
                    }
                    *(float2*)(out0 + (size_t)m * N + n) = make_float2(v0, v1);
                }
            }
        }
    }
}

// ---------------- flash attention: pure fp16, double-buffered Q/V --------------
// k'=64 (4 mma steps). stride 144B rows. 72KB smem -> 2 CTAs/SM.
constexpr uint32_t AQSTG  = 64u * 144;                  // 9216 per stage
constexpr uint32_t AOFF_K = 0;                          // 128 rows
constexpr uint32_t AOFF_Q = 128u * 144;                 // 18432 (2 stages)
constexpr uint32_t AOFF_V = AOFF_Q + 2 * AQSTG;         // 36864 (2 stages)
constexpr uint32_t AOFF_P = AOFF_V + 2 * AQSTG;         // 55296 (128 rows)
constexpr int ATTN2_SMEM = (int)(AOFF_P + 128u * 144);  // 73728

__global__ void __launch_bounds__(256)
attn_mma(const __half* __restrict__ Kc, const __half* __restrict__ Qc,
         const __half* __restrict__ Vt, __half* __restrict__ acat)
{
    extern __shared__ char smb[];
    uint32_t sb = smem_u32(smb);
    int tid = threadIdx.x, wid = tid >> 5, lane = tid & 31;
    int tt = blockIdx.x, h = blockIdx.y, b = blockIdx.z;
    int bh = b * H_ + h;
    const __half* Kg = Kc + ((size_t)bh * T_ + (size_t)tt * 128) * 64;
    const __half* Qg = Qc + (size_t)bh * T_ * 64;
    const __half* Vg = Vt + (size_t)bh * 64 * 256;

    // K tile: 128 rows x 8 chunks of 16B
    #pragma unroll
    for (int it = 0; it < 4; it++) {
        int ch = tid + it * 256;
        int r = ch >> 3, c = ch & 7;
        cp16(sb + AOFF_K + r * 144 + c * 16, Kg + (size_t)r * 64 + c * 8);
    }
    CP_COMMIT();

    int nst = tt * 2 + 2;
    auto loadQV = [&](int st) {
        int stg = st & 1;
        const __half* Qt = Qg + (size_t)st * 64 * 64;
        #pragma unroll
        for (int it = 0; it < 2; it++) {
            int ch = tid + it * 256;
            int r = ch >> 3, c = ch & 7;
            cp16(sb + AOFF_Q + stg * AQSTG + r * 144 + c * 16, Qt + (size_t)r * 64 + c * 8);
        }
        #pragma unroll
        for (int it = 0; it < 2; it++) {
            int ch = tid + it * 256;
            int r = ch >> 3, c = ch & 7;
            int gcol = st * 64 + c * 8;
            cp16(sb + AOFF_V + stg * AQSTG + r * 144 + c * 16, Vg + (size_t)r * 256 + gcol);
        }
        CP_COMMIT();
    };
    loadQV(0);

    float m_run[2] = { -CUDART_INF_F, -CUDART_INF_F };
    float l_run[2] = { 0.0f, 0.0f };
    float oacc[8][4];
    #pragma unroll
    for (int nt = 0; nt < 8; nt++)
        #pragma unroll
        for (int e = 0; e < 4; e++) oacc[nt][e] = 0.0f;

    const float scl = rsqrtf((float)C_);
    int q = lane >> 3, i5 = lane & 7;
    uint32_t aK = sb + AOFF_K + (wid * 16 + (q & 1) * 8 + i5) * 144 + (q >> 1) * 16;
    uint32_t aP = sb + AOFF_P + (wid * 16 + (q & 1) * 8 + i5) * 144 + (q >> 1) * 16;
    uint32_t bQ = sb + AOFF_Q + ((q >> 1) * 8 + i5) * 144 + (q & 1) * 16;
    uint32_t bV = sb + AOFF_V + ((q >> 1) * 8 + i5) * 144 + (q & 1) * 16;

    int r0 = lane >> 2;
    int tg0 = tt * 128 + wid * 16 + r0;
    int tg1 = tg0 + 8;
    __half* sP = (__half*)(smb + AOFF_P);

    for (int st = 0; st < nst; st++) {
        int stg = st & 1;
        if (st + 1 < nst) { loadQV(st + 1); CP_WAIT1(); } else { CP_WAIT0(); }
        __syncthreads();

        // S = K.Q : k'=64 (4 steps)
        float sacc[8][4];
        #pragma unroll
        for (int nt = 0; nt < 8; nt++)
            #pragma unroll
            for (int e = 0; e < 4; e++) sacc[nt][e] = 0.0f;
        #pragma unroll
        for (int ks = 0; ks < 4; ks++) {
            uint32_t af[4], bf[4][4];
            ldm_x4(af, aK + ks * 32);
            #pragma unroll
            for (int p = 0; p < 4; p++)
                ldm_x4(bf[p], bQ + stg * AQSTG + p * 16 * 144 + ks * 32);
            #pragma unroll
            for (int nt = 0; nt < 8; nt++)
                mma16816(sacc[nt], af, bf[nt >> 1][(nt & 1) * 2],
                         bf[nt >> 1][(nt & 1) * 2 + 1]);
        }

        float mx0 = -CUDART_INF_F, mx1 = -CUDART_INF_F;
        #pragma unroll
        for (int nt = 0; nt < 8; nt++) {
            #pragma unroll
            for (int e = 0; e < 2; e++) {
                int sg = st * 64 + nt * 8 + (lane & 3) * 2 + e;
                float v0 = sacc[nt][e] * scl;
                if (sg > tg0) v0 = -CUDART_INF_F;
                sacc[nt][e] = v0; mx0 = fmaxf(mx0, v0);
                float v1 = sacc[nt][2 + e] * scl;
                if (sg > tg1) v1 = -CUDART_INF_F;
                sacc[nt][2 + e] = v1; mx1 = fmaxf(mx1, v1);
            }
        }
        mx0 = fmaxf(mx0, __shfl_xor_sync(0xffffffffu, mx0, 1));
        mx0 = fmaxf(mx0, __shfl_xor_sync(0xffffffffu, mx0, 2));
        mx1 = fmaxf(mx1, __shfl_xor_sync(0xffffffffu, mx1, 1));
        mx1 = fmaxf(mx1, __shfl_xor_sync(0xffffffffu, mx1, 2));

        float mn0 = fmaxf(m_run[0], mx0), mn1 = fmaxf(m_run[1], mx1);
        float es0 = __expf(m_run[0] - mn0), es1 = __expf(m_run[1] - mn1);
        m_run[0] = mn0; m_run[1] = mn1;

        float sum0 = 0.0f, sum1 = 0.0f;
        #pragma unroll
        for (int nt = 0; nt < 8; nt++) {
            #pragma unroll
            for (int e = 0; e < 2; e++) {
                float p0 = __expf(sacc[nt][e] - mn0);     sacc[nt][e] = p0;     sum0 += p0;
                float p1 = __expf(sacc[nt][2 + e] - mn1); sacc[nt][2 + e] = p1; sum1 += p1;
            }
        }
        sum0 += __shfl_xor_sync(0xffffffffu, sum0, 1);
        sum0 += __shfl_xor_sync(0xffffffffu, sum0, 2);
        sum1 += __shfl_xor_sync(0xffffffffu, sum1, 1);
        sum1 += __shfl_xor_sync(0xffffffffu, sum1, 2);
        l_run[0] = l_run[0] * es0 + sum0;
        l_run[1] = l_run[1] * es1 + sum1;

        #pragma unroll
        for (int nt = 0; nt < 8; nt++) {
            oacc[nt][0] *= es0; oacc[nt][1] *= es0;
            oacc[nt][2] *= es1; oacc[nt][3] *= es1;
        }

        // write P fp16 (72-half row stride)
        #pragma unroll
        for (int nt = 0; nt < 8; nt++) {
            int cb = nt * 8 + (lane & 3) * 2;
            __half* pr = sP + (wid * 16 + r0) * 72 + cb;
            *(uint32_t*)(pr) = pack2f(sacc[nt][0], sacc[nt][1]);
            __half* pr2 = pr + 8 * 72;
            *(uint32_t*)(pr2) = pack2f(sacc[nt][2], sacc[nt][3]);
        }
        __syncthreads();

        // O += P.V : k'=64 (4 steps)
        #pragma unroll
        for (int ks = 0; ks < 4; ks++) {
            uint32_t af[4], bf[4][4];
            ldm_x4(af, aP + ks * 32);
            #pragma unroll
            for (int p = 0; p < 4; p++)
                ldm_x4(bf[p], bV + stg * AQSTG + p * 16 * 144 + ks * 32);
            #pragma unroll
            for (int nt = 0; nt < 8; nt++)
                mma16816(oacc[nt], af, bf[nt >> 1][(nt & 1) * 2],
                         bf[nt >> 1][(nt & 1) * 2 + 1]);
        }
        __syncthreads();
    }

    // epilogue: normalize, write acatA fp16 rows directly
    float inv0 = 1.0f / l_run[0], inv1 = 1.0f / l_run[1];
    int t0 = tt * 128 + wid * 16 + r0;
    size_t mrow0 = (size_t)(b * T_ + t0) * C_;
    size_t mrow1 = mrow0 + (size_t)8 * C_;
    #pragma unroll
    for (int nt = 0; nt < 8; nt++) {
        int k = h * 64 + nt * 8 + (lane & 3) * 2;
        *(uint32_t*)(g_acatA + mrow0 + k) = pack2f(oacc[nt][0] * inv0, oacc[nt][1] * inv0);
        *(uint32_t*)(g_acatA + mrow1 + k) = pack2f(oacc[nt][2] * inv1, oacc[nt][3] * inv1);
    }
}

// ---------------- host orchestration -------------------------------------------
extern "C" void kernel_launch(void* const* d_in, const int* in_sizes, int n_in,
                              void* d_out, int out_size)
{
    const float* x     = (const float*)d_in[0];
    const float* ln1_g = (const float*)d_in[1];
    const float* ln1_b = (const float*)d_in[2];
    const float* Wk    = (const float*)d_in[3];
    const float* bk    = (const float*)d_in[4];
    const float* Wq    = (const float*)d_in[5];
    const float* bq    = (const float*)d_in[6];
    const float* Wv    = (const float*)d_in[7];
    const float* bv    = (const float*)d_in[8];
    const float* Wp    = (const float*)d_in[9];
    const float* bp    = (const float*)d_in[10];
    const float* ln2_g = (const float*)d_in[11];
    const float* ln2_b = (const float*)d_in[12];
    const float* W1    = (const float*)d_in[13];
    const float* b1    = (const float*)d_in[14];
    const float* W2    = (const float*)d_in[15];
    const float* b2    = (const float*)d_in[16];
    float* out = (float*)d_out;

    __half *acatA, *acat4, *bqkv, *bcp, *bc1, *bc2, *kc, *qc, *vt;
    float *biasqkv, *x1;
    cudaGetSymbolAddress((void**)&acatA,   g_acatA);
    cudaGetSymbolAddress((void**)&acat4,   g_acat4);
    cudaGetSymbolAddress((void**)&bqkv,    g_bqkv);
    cudaGetSymbolAddress((void**)&bcp,     g_bcp);
    cudaGetSymbolAddress((void**)&bc1,     g_bc1);
    cudaGetSymbolAddress((void**)&bc2,     g_bc2);
    cudaGetSymbolAddress((void**)&biasqkv, g_biasqkv);
    cudaGetSymbolAddress((void**)&kc,  g_kc);
    cudaGetSymbolAddress((void**)&qc,  g_qc);
    cudaGetSymbolAddress((void**)&vt,  g_vt);
    cudaGetSymbolAddress((void**)&x1,  g_x1);

    cudaFuncSetAttribute(attn_mma, cudaFuncAttributeMaxDynamicSharedMemorySize, ATTN2_SMEM);
    cudaFuncSetAttribute(mma_gemm<1>, cudaFuncAttributeMaxDynamicSharedMemorySize, GEMM_SMEM);
    cudaFuncSetAttribute(mma_gemm<2>, cudaFuncAttributeMaxDynamicSharedMemorySize, GEMM_SMEM);
    cudaFuncSetAttribute(mma_gemm<4>, cudaFuncAttributeMaxDynamicSharedMemorySize, GEMM_SMEM);

    // weight / bias conversions
    bias_concat_kernel<<<5, 256>>>(bk, bq, bv, biasqkv);
    build_bh_qkv_kernel<<<(3 * C_ * C_ + 255) / 256, 256>>>(Wk, Wq, Wv, bqkv);
    build_bh_kernel<<<(C_ * C_ + 255) / 256, 256>>>(Wp, bcp, C_, C_);
    build_bh_kernel<<<(C_ * FF_ + 255) / 256, 256>>>(W1, bc1, C_, FF_);
    build_bh_kernel<<<(FF_ * C_ + 255) / 256, 256>>>(W2, bc2, FF_, C_);

    // 1. LN1 -> fp16 acatA
    ln_h_kernel<<<M_, 128>>>(x, ln1_g, ln1_b, acatA);

    // 2. fused QKV projection (K=384, N=1152)
    mma_gemm<1><<<dim3(9, M_ / 128), 256, GEMM_SMEM>>>(
        acatA, bqkv, biasqkv, nullptr, (float*)kc, (float*)qc, (float*)vt,
        nullptr, C_, 3 * C_);

    // 3. flash attention (writes proj input acatA directly)
    attn_mma<<<dim3(2, H_, B_), 256, ATTN2_SMEM>>>(kc, qc, vt, acatA);

    // 4. output projection + residual (K=384, N=384)
    mma_gemm<4><<<dim3(3, M_ / 128), 256, GEMM_SMEM>>>(
        acatA, bcp, bp, x, x1, nullptr, nullptr, nullptr, C_, C_);

    // 5. LN2 -> fp16 acatA
    ln_h_kernel<<<M_, 128>>>(x1, ln2_g, ln2_b, acatA);

    // 6. FFN up + ReLU -> fp16 acat4 (K=384, N=1536)
    mma_gemm<2><<<dim3(12, M_ / 128), 256, GEMM_SMEM>>>(
        acatA, bc1, b1, nullptr, nullptr, nullptr, nullptr, acat4, C_, FF_);

    // 7. FFN down + residual -> d_out (K=1536, N=384)
    mma_gemm<4><<<dim3(3, M_ / 128), 256, GEMM_SMEM>>>(
        acat4, bc2, b2, x1, out, nullptr, nullptr, nullptr, FF_, C_);
}